// round 8
// baseline (speedup 1.0000x reference)
#include <cuda_runtime.h>
#include <cstdio>
#include <cstdint>
#include <cstdlib>

// 1-NN codebook quantization.
// out[m] = argmin_k ||q_m - c_k||^2, q_m = x.flat[m*128 .. m*128+127]
// Indices written as FLOAT32 (hypothesis: harness output dtype is f32;
// int32 writes reinterpreted as f32 are ~0 -> the exact rel_err==1.0 seen
// in rounds 1-5).

#define C_DIM 128
#define KC    256
#define CHUNK 64               // codes per smem chunk (32 KB)
#define NCH   (KC / CHUNK)
#define GAP_T 0.05f            // fp32 top-2 ambiguity threshold -> fp64 rescue

__device__ int g_count;
__device__ int g_work[131072];

__global__ void k_reset() { g_count = 0; }

// ---------------- fast pass: fp32, one query row per thread ----------------
__global__ __launch_bounds__(256) void k_main(const float* __restrict__ x,
                                              const float* __restrict__ cbg,
                                              float* __restrict__ out) {
    __shared__ __align__(16) float scb[CHUNK * C_DIM];   // 32 KB
    __shared__ float scsq[CHUNK];

    const int  t   = threadIdx.x;
    const long row = (long)blockIdx.x * 256 + t;

    float q[C_DIM];
    {
        const float4* xr = reinterpret_cast<const float4*>(x + row * C_DIM);
        #pragma unroll
        for (int i = 0; i < C_DIM / 4; i++) {
            float4 v = xr[i];
            q[4 * i] = v.x; q[4 * i + 1] = v.y; q[4 * i + 2] = v.z; q[4 * i + 3] = v.w;
        }
    }

    float best = 3.4e38f, best2 = 3.4e38f;
    int   bi   = 0;

    const float4* cb4 = reinterpret_cast<const float4*>(cbg);

    for (int c = 0; c < NCH; c++) {
        if (c) __syncthreads();
        #pragma unroll
        for (int i = 0; i < 8; i++) {                    // 2048 float4 = 32 KB
            int e = t + i * 256;
            reinterpret_cast<float4*>(scb)[e] = cb4[c * (CHUNK * C_DIM / 4) + e];
        }
        __syncthreads();

        if (t < CHUNK) {                                 // in-block codebook norms
            const float4* cv = reinterpret_cast<const float4*>(scb) + t * 32;
            float s0 = 0.f, s1 = 0.f, s2 = 0.f, s3 = 0.f;
            #pragma unroll
            for (int j = 0; j < 32; j++) {
                float4 v = cv[(j + t) & 31];
                s0 = fmaf(v.x, v.x, s0); s1 = fmaf(v.y, v.y, s1);
                s2 = fmaf(v.z, v.z, s2); s3 = fmaf(v.w, v.w, s3);
            }
            scsq[t] = (s0 + s1) + (s2 + s3);
        }
        __syncthreads();

        #pragma unroll 1
        for (int k = 0; k < CHUNK; k++) {
            const float4* cv = reinterpret_cast<const float4*>(scb + k * C_DIM);
            float a0 = 0.f, a1 = 0.f, a2 = 0.f, a3 = 0.f;
            #pragma unroll
            for (int j = 0; j < C_DIM / 4; j++) {
                float4 cj = cv[j];                       // broadcast LDS.128
                a0 = fmaf(q[4 * j],     cj.x, a0);
                a1 = fmaf(q[4 * j + 1], cj.y, a1);
                a2 = fmaf(q[4 * j + 2], cj.z, a2);
                a3 = fmaf(q[4 * j + 3], cj.w, a3);
            }
            float d = fmaf(-2.f, (a0 + a2) + (a1 + a3), scsq[k]);
            int ki = c * CHUNK + k;
            if (d < best)       { best2 = best; best = d; bi = ki; }
            else if (d < best2) { best2 = d; }
        }
    }

    out[row] = (float)bi;                                // FLOAT output

    if (best2 - best < GAP_T) {                          // ambiguous -> rescue list
        int idx = atomicAdd(&g_count, 1);
        g_work[idx] = (int)row;
    }
}

// ---------------- rescue: warp-per-row exact fp64 argmin ----------------
__global__ void k_fix(const float* __restrict__ x,
                      const float* __restrict__ cb,
                      float* __restrict__ out) {
    const int lane   = threadIdx.x & 31;
    const int warp0  = (blockIdx.x * blockDim.x + threadIdx.x) >> 5;
    const int nwarps = (gridDim.x * blockDim.x) >> 5;
    const int n      = g_count;

    for (int w = warp0; w < n; w += nwarps) {
        const int    row = g_work[w];
        const float* qp  = x + (long)row * C_DIM;

        double best = 1e300; int bi = KC;
        #pragma unroll 1
        for (int kk = 0; kk < KC / 32; kk++) {           // 8 codes per lane, ascending
            int k = lane * (KC / 32) + kk;
            const float* cp = cb + k * C_DIM;
            double d0 = 0, d1 = 0, d2 = 0, d3 = 0;
            double c0 = 0, c1 = 0, c2 = 0, c3 = 0;
            #pragma unroll 4
            for (int j = 0; j < C_DIM; j += 4) {
                double v0 = cp[j], v1 = cp[j + 1], v2 = cp[j + 2], v3 = cp[j + 3];
                d0 = fma((double)qp[j],     v0, d0); c0 = fma(v0, v0, c0);
                d1 = fma((double)qp[j + 1], v1, d1); c1 = fma(v1, v1, c1);
                d2 = fma((double)qp[j + 2], v2, d2); c2 = fma(v2, v2, c2);
                d3 = fma((double)qp[j + 3], v3, d3); c3 = fma(v3, v3, c3);
            }
            double d = ((c0 + c1) + (c2 + c3)) - 2.0 * ((d0 + d1) + (d2 + d3));
            if (d < best) { best = d; bi = k; }          // strict '<': first wins
        }
        #pragma unroll
        for (int off = 16; off; off >>= 1) {             // lower index wins ties
            double ov = __shfl_down_sync(0xffffffffu, best, off);
            int    oi = __shfl_down_sync(0xffffffffu, bi,   off);
            if (ov < best || (ov == best && oi < bi)) { best = ov; bi = oi; }
        }
        if (lane == 0) out[row] = (float)bi;
    }
}

extern "C" void kernel_launch(void* const* d_in, const int* in_sizes, int n_in,
                              void* d_out, int out_size) {
    // x is the largest input; codebook is exactly 512x smaller (either unit).
    long xs = -1, cs = -1; int xi = 0, ci = 0;
    for (int i = 0; i < n_in; i++)
        if ((long)in_sizes[i] > xs) { xs = in_sizes[i]; xi = i; }
    for (int i = 0; i < n_in; i++)
        if (i != xi && in_sizes[i] * 512L == xs) { cs = in_sizes[i]; ci = i; }

    long scale = (cs > 0) ? cs / (KC * C_DIM) : -1;      // 1 = elements, 4 = bytes
    long M     = (scale > 0) ? xs / (C_DIM * scale) : -1;

    if (cs <= 0 || scale < 1 || cs != (long)KC * C_DIM * scale || (M % 256) != 0) {
        printf("[TRIPWIRE] size model mismatch: n_in=%d sizes=", n_in);
        for (int i = 0; i < n_in; i++) printf("%d ", in_sizes[i]);
        printf("out_size=%d\n", out_size);
        fflush(stdout);
        abort();                                          // rc!=0 -> log surfaces
    }

    const float* x  = (const float*)d_in[xi];
    const float* cb = (const float*)d_in[ci];

    k_reset<<<1, 1>>>();
    k_main<<<(int)(M / 256), 256>>>(x, cb, (float*)d_out);
    k_fix<<<128, 256>>>(x, cb, (float*)d_out);

    cudaError_t e = cudaGetLastError();
    if (e != cudaSuccess) {
        printf("[TRIPWIRE] launch error: %s\n", cudaGetErrorString(e));
        fflush(stdout);
        abort();
    }
}

// round 10
// speedup vs baseline: 1.0361x; 1.0361x over previous
#include <cuda_runtime.h>
#include <cstdio>
#include <cstdint>
#include <cstdlib>

// 1-NN codebook quantization.
// out[m] = argmin_k ||q_m - c_k||^2, q_m = x.flat[m*128 .. m*128+127]
// Output written as FLOAT32 (proven in R8: harness output dtype is f32).
//
// R9/R10: packed f32x2 FMA (2x fp32 rate on sm_103a). Channel pairs packed into
// 64-bit lanes: acc.lo sums even channels, acc.hi odd channels, dot = lo+hi.
// No layout changes needed — q rows and codebook rows are contiguous fp32.

#define C_DIM 128
#define KC    256
#define CHUNK 64               // codes per smem chunk (32 KB)
#define NCH   (KC / CHUNK)
#define GAP_T 0.05f            // fp32 top-2 ambiguity threshold -> fp64 rescue

typedef unsigned long long ull;

__device__ int g_count;
__device__ int g_work[131072];

__global__ void k_reset() { g_count = 0; }

// ---------------- fast pass: packed-f32x2 dot products, one row per thread ----------------
__global__ __launch_bounds__(256) void k_main(const float* __restrict__ x,
                                              const float* __restrict__ cbg,
                                              float* __restrict__ out) {
    __shared__ __align__(16) float scb[CHUNK * C_DIM];   // 32 KB
    __shared__ float scsq[CHUNK];

    const int  t   = threadIdx.x;
    const long row = (long)blockIdx.x * 256 + t;

    // this thread's query row -> 64 packed f32x2 registers
    ull q[C_DIM / 2];
    {
        const ulonglong2* xr = reinterpret_cast<const ulonglong2*>(x + row * C_DIM);
        #pragma unroll
        for (int i = 0; i < C_DIM / 4; i++) {
            ulonglong2 v = xr[i];
            q[2 * i]     = v.x;
            q[2 * i + 1] = v.y;
        }
    }

    float best = 3.4e38f, best2 = 3.4e38f;
    int   bi   = 0;

    const float4* cb4 = reinterpret_cast<const float4*>(cbg);

    for (int c = 0; c < NCH; c++) {
        if (c) __syncthreads();                          // previous chunk consumed
        #pragma unroll
        for (int i = 0; i < 8; i++) {                    // 2048 float4 = 32 KB
            int e = t + i * 256;
            reinterpret_cast<float4*>(scb)[e] = cb4[c * (CHUNK * C_DIM / 4) + e];
        }
        __syncthreads();

        if (t < CHUNK) {                                 // in-block codebook norms
            const float4* cv = reinterpret_cast<const float4*>(scb) + t * 32;
            float s0 = 0.f, s1 = 0.f, s2 = 0.f, s3 = 0.f;
            #pragma unroll
            for (int j = 0; j < 32; j++) {
                float4 v = cv[(j + t) & 31];             // rotated -> conflict-free
                s0 = fmaf(v.x, v.x, s0); s1 = fmaf(v.y, v.y, s1);
                s2 = fmaf(v.z, v.z, s2); s3 = fmaf(v.w, v.w, s3);
            }
            scsq[t] = (s0 + s1) + (s2 + s3);
        }
        __syncthreads();

        #pragma unroll 1
        for (int k = 0; k < CHUNK; k++) {
            const ulonglong2* cv =
                reinterpret_cast<const ulonglong2*>(scb + k * C_DIM);
            ull a0 = 0, a1 = 0, a2 = 0, a3 = 0;          // 4 independent chains
            #pragma unroll
            for (int j = 0; j < C_DIM / 4; j += 2) {     // 16 iters, 4 FFMA2 each
                ulonglong2 c0 = cv[j];                   // broadcast LDS.128
                ulonglong2 c1 = cv[j + 1];
                asm("fma.rn.f32x2 %0, %1, %2, %0;" : "+l"(a0) : "l"(q[2 * j]),     "l"(c0.x));
                asm("fma.rn.f32x2 %0, %1, %2, %0;" : "+l"(a1) : "l"(q[2 * j + 1]), "l"(c0.y));
                asm("fma.rn.f32x2 %0, %1, %2, %0;" : "+l"(a2) : "l"(q[2 * j + 2]), "l"(c1.x));
                asm("fma.rn.f32x2 %0, %1, %2, %0;" : "+l"(a3) : "l"(q[2 * j + 3]), "l"(c1.y));
            }
            asm("add.rn.f32x2 %0, %0, %1;" : "+l"(a0) : "l"(a2));
            asm("add.rn.f32x2 %0, %0, %1;" : "+l"(a1) : "l"(a3));
            asm("add.rn.f32x2 %0, %0, %1;" : "+l"(a0) : "l"(a1));
            float lo, hi;
            asm("mov.b64 {%0, %1}, %2;" : "=f"(lo), "=f"(hi) : "l"(a0));
            float d = fmaf(-2.f, lo + hi, scsq[k]);
            int ki = c * CHUNK + k;
            if (d < best)       { best2 = best; best = d; bi = ki; }
            else if (d < best2) { best2 = d; }
        }
    }

    out[row] = (float)bi;                                // FLOAT output (proven)

    if (best2 - best < GAP_T) {                          // ambiguous -> rescue list
        int idx = atomicAdd(&g_count, 1);
        g_work[idx] = (int)row;
    }
}

// ---------------- rescue: warp-per-row exact fp64 argmin ----------------
__global__ void k_fix(const float* __restrict__ x,
                      const float* __restrict__ cb,
                      float* __restrict__ out) {
    const int lane   = threadIdx.x & 31;
    const int warp0  = (blockIdx.x * blockDim.x + threadIdx.x) >> 5;
    const int nwarps = (gridDim.x * blockDim.x) >> 5;
    const int n      = g_count;

    for (int w = warp0; w < n; w += nwarps) {
        const int    row = g_work[w];
        const float* qp  = x + (long)row * C_DIM;

        double best = 1e300; int bi = KC;
        #pragma unroll 1
        for (int kk = 0; kk < KC / 32; kk++) {           // 8 codes per lane, ascending
            int k = lane * (KC / 32) + kk;
            const float* cp = cb + k * C_DIM;
            double d0 = 0, d1 = 0, d2 = 0, d3 = 0;
            double c0 = 0, c1 = 0, c2 = 0, c3 = 0;
            #pragma unroll 4
            for (int j = 0; j < C_DIM; j += 4) {
                double v0 = cp[j], v1 = cp[j + 1], v2 = cp[j + 2], v3 = cp[j + 3];
                d0 = fma((double)qp[j],     v0, d0); c0 = fma(v0, v0, c0);
                d1 = fma((double)qp[j + 1], v1, d1); c1 = fma(v1, v1, c1);
                d2 = fma((double)qp[j + 2], v2, d2); c2 = fma(v2, v2, c2);
                d3 = fma((double)qp[j + 3], v3, d3); c3 = fma(v3, v3, c3);
            }
            double d = ((c0 + c1) + (c2 + c3)) - 2.0 * ((d0 + d1) + (d2 + d3));
            if (d < best) { best = d; bi = k; }          // strict '<': first wins
        }
        #pragma unroll
        for (int off = 16; off; off >>= 1) {             // lower index wins ties
            double ov = __shfl_down_sync(0xffffffffu, best, off);
            int    oi = __shfl_down_sync(0xffffffffu, bi,   off);
            if (ov < best || (ov == best && oi < bi)) { best = ov; bi = oi; }
        }
        if (lane == 0) out[row] = (float)bi;
    }
}

extern "C" void kernel_launch(void* const* d_in, const int* in_sizes, int n_in,
                              void* d_out, int out_size) {
    // x is the largest input; codebook is exactly 512x smaller (either unit).
    long xs = -1, cs = -1; int xi = 0, ci = 0;
    for (int i = 0; i < n_in; i++)
        if ((long)in_sizes[i] > xs) { xs = in_sizes[i]; xi = i; }
    for (int i = 0; i < n_in; i++)
        if (i != xi && in_sizes[i] * 512L == xs) { cs = in_sizes[i]; ci = i; }

    long scale = (cs > 0) ? cs / (KC * C_DIM) : -1;      // 1 = elements, 4 = bytes
    long M     = (scale > 0) ? xs / (C_DIM * scale) : -1;

    if (cs <= 0 || scale < 1 || cs != (long)KC * C_DIM * scale || (M % 256) != 0) {
        printf("[TRIPWIRE] size model mismatch: n_in=%d sizes=", n_in);
        for (int i = 0; i < n_in; i++) printf("%d ", in_sizes[i]);
        printf("out_size=%d\n", out_size);
        fflush(stdout);
        abort();
    }

    const float* x  = (const float*)d_in[xi];
    const float* cb = (const float*)d_in[ci];

    k_reset<<<1, 1>>>();
    k_main<<<(int)(M / 256), 256>>>(x, cb, (float*)d_out);
    k_fix<<<128, 256>>>(x, cb, (float*)d_out);

    cudaError_t e = cudaGetLastError();
    if (e != cudaSuccess) {
        printf("[TRIPWIRE] launch error: %s\n", cudaGetErrorString(e));
        fflush(stdout);
        abort();
    }
}

// round 11
// speedup vs baseline: 1.1255x; 1.0863x over previous
#include <cuda_runtime.h>
#include <cstdio>
#include <cstdint>
#include <cstdlib>

// 1-NN codebook quantization (float32 output indices, proven R8).
// R11: register-tiled GEMM. CTA = 128 rows x 256 codes, thread tile
// 8 row-pairs x 8 codes in packed f32x2 accumulators. Per channel:
// 8 LDS.128 feed 64 FFMA2 (was 32 LDS per 64 FFMA2) -> LDS-bound fixed.
// In-CTA transpose of x into [ch][row-pair] smem, codebook duplicated {c,c}.
// Pad-5 unit layout => conflict-free LDS.128 on both operands.

#define C_DIM 128
#define KC    256
#define GAP_T 0.05f

typedef unsigned long long ull;

__device__ float g_csq[KC];
__device__ int   g_count;
__device__ int   g_work[131072];

// order-preserving float<->uint (for packed value|index argmin)
__device__ __forceinline__ unsigned enc(float f) {
    unsigned u = __float_as_uint(f);
    return (u >> 31) ? ~u : (u | 0x80000000u);
}
__device__ __forceinline__ float dec(unsigned e) {
    return __uint_as_float((e >> 31) ? (e ^ 0x80000000u) : ~e);
}

// ---- prepass: codebook squared norms + worklist reset ----
__global__ void k_csq(const float* __restrict__ cb) {
    int k = threadIdx.x;
    if (k == 0) g_count = 0;
    if (k >= KC) return;
    float s = 0.f;
    #pragma unroll 4
    for (int i = 0; i < C_DIM; i++) { float v = cb[k * C_DIM + i]; s = fmaf(v, v, s); }
    g_csq[k] = s;
}

// ---- main: tiled GEMM + argmin ----
// smem GEMM phase: q  [8 ch][40 units]  (unit = 16B = 2 row-pair float2) = 5120 B
//                  cb [8 ch][160 units] (unit = 2 duplicated codes)      = 20480 B
// smem epi  phase: cand u64 [32 cg][128 rows] = 32768 B ; b2e u32 [32][128] = 16384 B
__global__ __launch_bounds__(256) void k_main(const float* __restrict__ x,
                                              const float* __restrict__ cbg,
                                              float* __restrict__ out) {
    __shared__ __align__(16) unsigned char smem[49152];
    float*    sqf  = (float*)smem;
    float2*   scb2 = (float2*)(smem + 5120);
    ull*      cand = (ull*)smem;
    unsigned* b2e  = (unsigned*)(smem + 32768);

    const int t    = threadIdx.x;
    const int pg   = t & 7;          // pair-group: pairs [8pg, 8pg+8)
    const int cg   = t >> 3;         // code-group: codes [8cg, 8cg+8)
    const int row0 = blockIdx.x * 128;

    ull acc[64];
    #pragma unroll
    for (int i = 0; i < 64; i++) acc[i] = 0ull;

    // global-load roles
    const int r_ = t >> 1, h_ = t & 1;                       // x: row r_, half h_
    const float* xrow  = x + (long)(row0 + r_) * C_DIM + h_ * 4;
    const float* cbrow = cbg + t * C_DIM;                    // cb: code t
    const int ug = (t >> 3) * 5 + ((t >> 1) & 3);            // code unit (pad-5)
    const int sl = t & 1;

    float4 xa  = *(const float4*)xrow;                       // prefetch chunk 0
    float4 ca  = *(const float4*)cbrow;
    float4 ca2 = *(const float4*)(cbrow + 4);

    #pragma unroll 1
    for (int cc = 0; cc < 16; cc++) {
        // stage prefetched chunk into smem
        {
            const float* v = (const float*)&xa;
            #pragma unroll
            for (int j2 = 0; j2 < 4; j2++) {
                int j  = 4 * h_ + j2;
                int fi = (j * 40 + (r_ >> 4) * 5 + ((r_ >> 2) & 3)) * 4 + (r_ & 3);
                sqf[fi] = v[j2];
            }
            const float* w  = (const float*)&ca;
            const float* w2 = (const float*)&ca2;
            #pragma unroll
            for (int j2 = 0; j2 < 4; j2++) {
                scb2[(j2 * 160 + ug) * 2 + sl]       = make_float2(w[j2],  w[j2]);
                scb2[((j2 + 4) * 160 + ug) * 2 + sl] = make_float2(w2[j2], w2[j2]);
            }
        }
        __syncthreads();
        if (cc + 1 < 16) {                                   // prefetch next chunk
            int c0 = (cc + 1) * 8;
            xa  = *(const float4*)(xrow + c0);
            ca  = *(const float4*)(cbrow + c0);
            ca2 = *(const float4*)(cbrow + c0 + 4);
        }
        // compute: 8 channels x (8 LDS.128 + 64 FFMA2)
        const ulonglong2* squ = (const ulonglong2*)smem;
        const ulonglong2* scu = (const ulonglong2*)(smem + 5120);
        #pragma unroll
        for (int j = 0; j < 8; j++) {
            ull qv[8], cv[8];
            int bq = j * 40  + pg * 5;
            int bc = j * 160 + cg * 5;
            #pragma unroll
            for (int u = 0; u < 4; u++) {
                ulonglong2 a = squ[bq + u]; qv[2 * u] = a.x; qv[2 * u + 1] = a.y;
                ulonglong2 b = scu[bc + u]; cv[2 * u] = b.x; cv[2 * u + 1] = b.y;
            }
            #pragma unroll
            for (int p = 0; p < 8; p++)
                #pragma unroll
                for (int v = 0; v < 8; v++)
                    asm("fma.rn.f32x2 %0, %1, %2, %0;"
                        : "+l"(acc[p * 8 + v]) : "l"(qv[p]), "l"(cv[v]));
        }
        __syncthreads();                                     // before next stage
    }

    // ---- epilogue: per-row packed argmin + second-best ----
    float csq[8];
    #pragma unroll
    for (int v = 0; v < 8; v++) csq[v] = __ldg(&g_csq[cg * 8 + v]);

    #pragma unroll
    for (int p = 0; p < 8; p++) {
        int r0 = (pg * 8 + p) * 2;                           // CTA-local rows r0, r0+1
        ull bp0 = ~0ull, bp1 = ~0ull;
        unsigned s0 = ~0u, s1 = ~0u;
        #pragma unroll
        for (int v = 0; v < 8; v++) {
            float lo, hi;
            asm("mov.b64 {%0, %1}, %2;" : "=f"(lo), "=f"(hi) : "l"(acc[p * 8 + v]));
            unsigned ki = (unsigned)(cg * 8 + v);
            ull k0 = ((ull)enc(fmaf(-2.f, lo, csq[v])) << 32) | ki;
            ull k1 = ((ull)enc(fmaf(-2.f, hi, csq[v])) << 32) | ki;
            if (k0 < bp0) { unsigned o = (unsigned)(bp0 >> 32); if (o < s0) s0 = o; bp0 = k0; }
            else          { unsigned e = (unsigned)(k0  >> 32); if (e < s0) s0 = e; }
            if (k1 < bp1) { unsigned o = (unsigned)(bp1 >> 32); if (o < s1) s1 = o; bp1 = k1; }
            else          { unsigned e = (unsigned)(k1  >> 32); if (e < s1) s1 = e; }
        }
        cand[cg * 128 + r0]     = bp0;  b2e[cg * 128 + r0]     = s0;
        cand[cg * 128 + r0 + 1] = bp1;  b2e[cg * 128 + r0 + 1] = s1;
    }
    __syncthreads();

    if (t < 128) {                                           // row t: reduce 32 groups
        ull bp = ~0ull; unsigned b2 = ~0u;
        #pragma unroll 8
        for (int g = 0; g < 32; g++) {
            ull pk = cand[g * 128 + t];
            unsigned s = b2e[g * 128 + t];
            if (pk < bp) { unsigned o = (unsigned)(bp >> 32); if (o < b2) b2 = o; bp = pk; }
            else         { unsigned e = (unsigned)(pk >> 32); if (e < b2) b2 = e; }
            if (s < b2) b2 = s;
        }
        out[row0 + t] = (float)(int)(unsigned)bp;            // low 32 bits = index
        if (dec(b2) - dec((unsigned)(bp >> 32)) < GAP_T) {   // ambiguous -> rescue
            int i = atomicAdd(&g_count, 1);
            g_work[i] = row0 + t;
        }
    }
}

// ---- rescue: warp-per-row exact fp64 argmin (proven R8/R10) ----
__global__ void k_fix(const float* __restrict__ x,
                      const float* __restrict__ cb,
                      float* __restrict__ out) {
    const int lane   = threadIdx.x & 31;
    const int warp0  = (blockIdx.x * blockDim.x + threadIdx.x) >> 5;
    const int nwarps = (gridDim.x * blockDim.x) >> 5;
    const int n      = g_count;

    for (int w = warp0; w < n; w += nwarps) {
        const int    row = g_work[w];
        const float* qp  = x + (long)row * C_DIM;
        double best = 1e300; int bi = KC;
        #pragma unroll 1
        for (int kk = 0; kk < KC / 32; kk++) {
            int k = lane * (KC / 32) + kk;
            const float* cp = cb + k * C_DIM;
            double d0 = 0, d1 = 0, d2 = 0, d3 = 0, c0 = 0, c1 = 0, c2 = 0, c3 = 0;
            #pragma unroll 4
            for (int j = 0; j < C_DIM; j += 4) {
                double v0 = cp[j], v1 = cp[j + 1], v2 = cp[j + 2], v3 = cp[j + 3];
                d0 = fma((double)qp[j],     v0, d0); c0 = fma(v0, v0, c0);
                d1 = fma((double)qp[j + 1], v1, d1); c1 = fma(v1, v1, c1);
                d2 = fma((double)qp[j + 2], v2, d2); c2 = fma(v2, v2, c2);
                d3 = fma((double)qp[j + 3], v3, d3); c3 = fma(v3, v3, c3);
            }
            double d = ((c0 + c1) + (c2 + c3)) - 2.0 * ((d0 + d1) + (d2 + d3));
            if (d < best) { best = d; bi = k; }
        }
        #pragma unroll
        for (int off = 16; off; off >>= 1) {
            double ov = __shfl_down_sync(0xffffffffu, best, off);
            int    oi = __shfl_down_sync(0xffffffffu, bi,   off);
            if (ov < best || (ov == best && oi < bi)) { best = ov; bi = oi; }
        }
        if (lane == 0) out[row] = (float)bi;
    }
}

extern "C" void kernel_launch(void* const* d_in, const int* in_sizes, int n_in,
                              void* d_out, int out_size) {
    long xs = -1, cs = -1; int xi = 0, ci = 0;
    for (int i = 0; i < n_in; i++)
        if ((long)in_sizes[i] > xs) { xs = in_sizes[i]; xi = i; }
    for (int i = 0; i < n_in; i++)
        if (i != xi && in_sizes[i] * 512L == xs) { cs = in_sizes[i]; ci = i; }

    long scale = (cs > 0) ? cs / (KC * C_DIM) : -1;
    long M     = (scale > 0) ? xs / (C_DIM * scale) : -1;

    if (cs <= 0 || scale < 1 || cs != (long)KC * C_DIM * scale || (M % 128) != 0) {
        printf("[TRIPWIRE] size model mismatch: n_in=%d sizes=", n_in);
        for (int i = 0; i < n_in; i++) printf("%d ", in_sizes[i]);
        printf("out_size=%d\n", out_size);
        fflush(stdout);
        abort();
    }

    const float* x  = (const float*)d_in[xi];
    const float* cb = (const float*)d_in[ci];

    k_csq<<<1, 256>>>(cb);
    k_main<<<(int)(M / 128), 256>>>(x, cb, (float*)d_out);
    k_fix<<<128, 256>>>(x, cb, (float*)d_out);

    cudaError_t e = cudaGetLastError();
    if (e != cudaSuccess) {
        printf("[TRIPWIRE] launch error: %s\n", cudaGetErrorString(e));
        fflush(stdout);
        abort();
    }
}